// round 15
// baseline (speedup 1.0000x reference)
#include <cuda_runtime.h>
#include <cuda_bf16.h>
#include <math.h>
#include <stdint.h>

#define S_  256
#define B_  64
#define E_  300
#define H_  512
#define G3  1536          // 3*H
#define NCLS 21

// ---------------- scratch (device globals; no allocation allowed) ----------------
__device__ float g_gi_f[(size_t)S_ * B_ * G3];     // [s][b][1536]
__device__ float g_gi_b[(size_t)S_ * B_ * G3];     // backward, time-reversed storage
__device__ float g_hf[(size_t)S_ * B_ * H_];       // fp32 h for head
__device__ float g_hb[(size_t)S_ * B_ * H_];
__device__ __nv_bfloat16 g_h16f[(size_t)S_ * B_ * H_];  // bf16 h (fallback path)
__device__ __nv_bfloat16 g_h16b[(size_t)S_ * B_ * H_];
__device__ unsigned g_flag[2][2][32][8];           // fallback flags

// ---------------- common helpers ----------------
__device__ __forceinline__ void mma_tf32(float c[4],
    uint32_t a0, uint32_t a1, uint32_t a2, uint32_t a3,
    uint32_t b0, uint32_t b1)
{
    asm volatile(
        "mma.sync.aligned.m16n8k8.row.col.f32.tf32.tf32.f32 "
        "{%0,%1,%2,%3},{%4,%5,%6,%7},{%8,%9},{%0,%1,%2,%3};"
        : "+f"(c[0]), "+f"(c[1]), "+f"(c[2]), "+f"(c[3])
        : "r"(a0), "r"(a1), "r"(a2), "r"(a3), "r"(b0), "r"(b1));
}

__device__ __forceinline__ void mma_bf16(float c[4],
    uint32_t a0, uint32_t a1, uint32_t a2, uint32_t a3,
    uint32_t b0, uint32_t b1)
{
    asm volatile(
        "mma.sync.aligned.m16n8k16.row.col.f32.bf16.bf16.f32 "
        "{%0,%1,%2,%3},{%4,%5,%6,%7},{%8,%9},{%0,%1,%2,%3};"
        : "+f"(c[0]), "+f"(c[1]), "+f"(c[2]), "+f"(c[3])
        : "r"(a0), "r"(a1), "r"(a2), "r"(a3), "r"(b0), "r"(b1));
}

__device__ __forceinline__ uint32_t pack_bf16(float lo, float hi) {
    uint32_t r;
    asm("cvt.rn.bf16x2.f32 %0, %1, %2;" : "=r"(r) : "f"(hi), "f"(lo));
    return r;
}

__device__ __forceinline__ unsigned ld_acquire(unsigned* p) {
    unsigned v;
    asm volatile("ld.acquire.gpu.global.u32 %0,[%1];" : "=r"(v) : "l"(p) : "memory");
    return v;
}

__device__ __forceinline__ void st_release(unsigned* p, unsigned v) {
    asm volatile("st.release.gpu.global.u32 [%0],%1;" :: "l"(p), "r"(v) : "memory");
}

__device__ __forceinline__ uint32_t smem_u32(const void* p) {
    uint32_t a;
    asm("{ .reg .u64 t; cvta.to.shared.u64 t, %1; cvt.u32.u64 %0, t; }"
        : "=r"(a) : "l"(p));
    return a;
}

__device__ __forceinline__ void cp_async16(uint32_t dst, const void* src, unsigned srcbytes) {
    asm volatile("cp.async.cg.shared.global [%0], [%1], 16, %2;"
                 :: "r"(dst), "l"(src), "r"(srcbytes));
}

__device__ __forceinline__ uint32_t mapa_u32(uint32_t a, unsigned rk) {
    uint32_t r;
    asm("mapa.shared::cluster.u32 %0, %1, %2;" : "=r"(r) : "r"(a), "r"(rk));
    return r;
}

__device__ __forceinline__ void stsc_u32(uint32_t addr, uint32_t v) {
    asm volatile("st.shared::cluster.u32 [%0], %1;" :: "r"(addr), "r"(v) : "memory");
}

__device__ __forceinline__ void mbar_init(uint32_t mbar, unsigned cnt) {
    asm volatile("mbarrier.init.shared.b64 [%0], %1;" :: "r"(mbar), "r"(cnt) : "memory");
}

__device__ __forceinline__ void mbar_arrive_peer(uint32_t local_mbar, unsigned rank) {
    asm volatile(
        "{\n\t"
        ".reg .b32 ra;\n\t"
        "mapa.shared::cluster.u32 ra, %0, %1;\n\t"
        "mbarrier.arrive.release.cluster.shared::cluster.b64 _, [ra];\n\t"
        "}"
        :: "r"(local_mbar), "r"(rank) : "memory");
}

__device__ __forceinline__ void mbar_wait_cluster(uint32_t mbar, unsigned parity) {
    asm volatile(
        "{\n\t"
        ".reg .pred P1;\n\t"
        "WL%=:\n\t"
        "mbarrier.try_wait.parity.acquire.cluster.shared::cta.b64 P1, [%0], %1, 0x989680;\n\t"
        "@P1 bra.uni WD%=;\n\t"
        "bra.uni WL%=;\n\t"
        "WD%=:\n\t"
        "}"
        :: "r"(mbar), "r"(parity) : "memory");
}

__device__ __forceinline__ float sigm_f(float x) {
    return __fdividef(1.f, 1.f + __expf(-x));
}
__device__ __forceinline__ float tanh_f(float x) {
    const float ax = fabsf(x);
    const float e  = __expf(-2.f * ax);
    const float r  = __fdividef(1.f - e, 1.f + e);
    return copysignf(r, x);
}

// =================================================================================
// Kernel A: gi = gather(emb, idx) @ W_ih^T + b_ih — tf32 MMA, 3-stage cp.async
// ring, ONE __syncthreads per k-tile (reuse distance 3).
// =================================================================================
#define TKP 20
#define SMEM_A_BYTES (2 * 3 * 128 * TKP * 4)

__global__ void __launch_bounds__(256, 2) gi_gemm_kernel(
    const int* __restrict__ idxmat, const float* __restrict__ emb,
    const float* __restrict__ Wf, const float* __restrict__ bf,
    const float* __restrict__ Wb, const float* __restrict__ bbias)
{
    extern __shared__ uint32_t gsm[];
    uint32_t (*As)[TKP] = (uint32_t (*)[TKP])(gsm);                    // [3*128][TKP]
    uint32_t (*Bs)[TKP] = (uint32_t (*)[TKP])(gsm + 3 * 128 * TKP);

    const int t    = threadIdx.x;
    const int n0   = blockIdx.x * 128;
    const int m0   = blockIdx.y * 128;
    const bool bwd = (n0 >= G3);

    const int lr = t & 127;       // row this thread copies
    const int kh = t >> 7;        // k-half (0 or 1)

    const int am = m0 + lr;
    const int srow = am >> 6, brow = am & 63;
    const float* arow = emb + (size_t)idxmat[brow * S_ + srow] * E_;

    const int ng = n0 + lr;
    const float* wrow = bwd ? (Wb + (size_t)(ng - G3) * E_)
                            : (Wf + (size_t)ng * E_);

    const int lane = t & 31;
    const int w    = t >> 5;
    const int gq   = lane >> 2, tig = lane & 3;
    const int mw   = (w & 3) * 32;
    const int nw   = (w >> 2) * 64;

    float acc[2][8][4];
#pragma unroll
    for (int mt = 0; mt < 2; mt++)
#pragma unroll
        for (int nt = 0; nt < 8; nt++)
#pragma unroll
            for (int i = 0; i < 4; i++) acc[mt][nt][i] = 0.f;

    const uint32_t sA0 = smem_u32(&As[lr][8 * kh]);
    const uint32_t sB0 = smem_u32(&Bs[lr][8 * kh]);
    const uint32_t bstr = 128 * TKP * 4;   // bytes per buffer

#define GI_ISSUE(TILE, BUF)                                            \
    {                                                                  \
        const int ka = (TILE) * 16 + 8 * kh;                           \
        const unsigned p0 = (ka < E_) ? 16u : 0u;                      \
        const unsigned p1 = (ka + 4 < E_) ? 16u : 0u;                  \
        cp_async16(sA0 + (BUF) * bstr,      arow + ka,     p0);        \
        cp_async16(sA0 + (BUF) * bstr + 16, arow + ka + 4, p1);        \
        cp_async16(sB0 + (BUF) * bstr,      wrow + ka,     p0);        \
        cp_async16(sB0 + (BUF) * bstr + 16, wrow + ka + 4, p1);        \
    }

    GI_ISSUE(0, 0); asm volatile("cp.async.commit_group;");
    GI_ISSUE(1, 1); asm volatile("cp.async.commit_group;");

    for (int tile = 0; tile < 19; tile++) {
        asm volatile("cp.async.wait_group 1;");
        __syncthreads();
        if (tile + 2 < 19) { GI_ISSUE(tile + 2, (tile + 2) % 3); }
        asm volatile("cp.async.commit_group;");

        const int bi = (tile % 3) * 128;
#pragma unroll
        for (int kt = 0; kt < 2; kt++) {
            const int kb = kt * 8;
            uint32_t a[2][4];
#pragma unroll
            for (int mt = 0; mt < 2; mt++) {
                const int mb = mw + mt * 16;
                a[mt][0] = As[bi + mb + gq][kb + tig];
                a[mt][1] = As[bi + mb + gq + 8][kb + tig];
                a[mt][2] = As[bi + mb + gq][kb + tig + 4];
                a[mt][3] = As[bi + mb + gq + 8][kb + tig + 4];
            }
#pragma unroll
            for (int nt = 0; nt < 8; nt++) {
                const int nb = nw + nt * 8 + gq;
                const uint32_t b0v = Bs[bi + nb][kb + tig];
                const uint32_t b1v = Bs[bi + nb][kb + tig + 4];
                mma_tf32(acc[0][nt], a[0][0], a[0][1], a[0][2], a[0][3], b0v, b1v);
                mma_tf32(acc[1][nt], a[1][0], a[1][1], a[1][2], a[1][3], b0v, b1v);
            }
        }
    }
#undef GI_ISSUE

    const float* bias = bwd ? bbias : bf;
    float* gbase = bwd ? g_gi_b : g_gi_f;
    const int nc0 = (bwd ? n0 - G3 : n0) + nw;

#pragma unroll
    for (int mt = 0; mt < 2; mt++) {
#pragma unroll
        for (int half = 0; half < 2; half++) {
            const int rm = m0 + mw + mt * 16 + gq + half * 8;
            const int si = rm >> 6, bi2 = rm & 63;
            const size_t mrow = bwd ? ((size_t)(S_ - 1 - si) * B_ + bi2) : (size_t)rm;
            float* dst = gbase + mrow * G3;
#pragma unroll
            for (int nt = 0; nt < 8; nt++) {
                const int c = nc0 + nt * 8 + 2 * tig;
                float2 v;
                v.x = acc[mt][nt][half * 2 + 0] + bias[c];
                v.y = acc[mt][nt][half * 2 + 1] + bias[c + 1];
                *(float2*)(dst + c) = v;
            }
        }
    }
}

// =================================================================================
// Kernel B (primary): cluster-16 DSMEM GRU scan.
// 128 blocks = dir(2) x bq(4: 16 batches) x jblk/rank(16: 32 units -> 96 rows).
// Cluster = (dir,bq): 16 CTAs. h exchanged by st.shared::cluster push into every
// peer's smem tile (double-buffered) + ping-pong mbarriers (release/acquire
// cluster scope). 8 warps = k-eighth; A-frags (96 u32) register-resident.
// =================================================================================
#define TILEW 260     // tile pitch in u32 (bank-conflict-free: 260 % 32 == 4)
#define BUFP2 18      // partial buf pitch (even => aligned float2)
#define SMEM_SC_BYTES ((2 * 16 * TILEW + 8 * 96 * BUFP2) * 4)

__global__ void __launch_bounds__(256, 1) gru_scan_cluster(
    const float* __restrict__ Whh_f, const float* __restrict__ bhh_f,
    const float* __restrict__ Whh_b, const float* __restrict__ bhh_b)
{
    extern __shared__ float sm[];
    uint32_t* tile = (uint32_t*)sm;              // [2][16][TILEW] bf16x2 of h
    float* buf = sm + 2 * 16 * TILEW;            // [8*96][BUFP2] mma partials
    __shared__ float bbv[96];
    __shared__ unsigned long long mbarst[2];
    __shared__ uint32_t ptb[16];                 // mapa'd peer tile bases

    const int t    = threadIdx.x;
    const int lane = t & 31;
    const int kg   = t >> 5;          // warp = k-eighth 0..7
    const int gq   = lane >> 2;
    const int tig  = lane & 3;

    const int blk  = blockIdx.x;
    const int dir  = blk >> 6;
    const int rank = blk & 15;        // == %cluster_ctarank
    const int j0   = rank * 32;
    const int b0   = ((blk >> 4) & 3) * 16;

    const float* Whh = dir ? Whh_b : Whh_f;
    const float* bhh = dir ? bhh_b : bhh_f;
    const float* gi  = dir ? g_gi_b : g_gi_f;
    float* hout32    = dir ? g_hb : g_hf;

    const uint32_t mb0 = smem_u32(&mbarst[0]);
    const uint32_t mb1 = smem_u32(&mbarst[1]);
    const uint32_t tbase = smem_u32(tile);

    if (t == 0) { mbar_init(mb0, 16u); mbar_init(mb1, 16u); }
    if (t < 96) bbv[t] = bhh[(size_t)((t >> 5) * 512 + j0 + (t & 31))];
    if (t < 16) ptb[t] = mapa_u32(tbase, (unsigned)t);

    // ---- register-resident bf16 A-fragments: a[mt][kt][4] for 6 m16 tiles ----
    uint32_t a[6][4][4];
#pragma unroll
    for (int mt = 0; mt < 6; mt++) {
        const int rr1 = mt * 16 + gq;
        const int rr2 = rr1 + 8;
        const float* w1 = Whh + (size_t)(((rr1 >> 5) << 9) + j0 + (rr1 & 31)) * 512;
        const float* w2 = Whh + (size_t)(((rr2 >> 5) << 9) + j0 + (rr2 & 31)) * 512;
#pragma unroll
        for (int kt = 0; kt < 4; kt++) {
            const int c0 = kg * 64 + kt * 16 + 2 * tig;
            const int c1 = c0 + 8;
            a[mt][kt][0] = pack_bf16(w1[c0], w1[c0 + 1]);
            a[mt][kt][1] = pack_bf16(w2[c0], w2[c0 + 1]);
            a[mt][kt][2] = pack_bf16(w1[c1], w1[c1 + 1]);
            a[mt][kt][3] = pack_bf16(w2[c1], w2[c1 + 1]);
        }
    }
    __syncthreads();
    // mbarriers + tables visible cluster-wide before any arrive/push
    asm volatile("barrier.cluster.arrive.aligned;" ::: "memory");
    asm volatile("barrier.cluster.wait.aligned;" ::: "memory");

    // combine coordinates: thread -> (batch b, unit pair 2jp/2jp+1)
    const int b  = t & 15;
    const int jp = t >> 4;            // 0..15
    const uint32_t myoff = (uint32_t)((b * TILEW + rank * 16 + jp) * 4);
    float hpA = 0.f, hpB = 0.f;

    for (int s = 0; s < S_; ++s) {
        // ---- prefetch gi[s] (overlaps wait) ----
        const float* gis = gi + (size_t)s * (B_ * G3);
        const size_t ga = (size_t)(b0 + b) * G3 + j0 + 2 * jp;
        const float2 ir2 = *(const float2*)(gis + ga);
        const float2 iz2 = *(const float2*)(gis + ga + 512);
        const float2 in2 = *(const float2*)(gis + ga + 1024);

        if (s > 0) {
            // ---- wait h[s-1]: ping-pong mbarrier, acquire cluster ----
            mbar_wait_cluster(((s - 1) & 1) ? mb1 : mb0, (unsigned)(((s - 1) >> 1) & 1));

            const uint32_t* ts = tile + ((s - 1) & 1) * (16 * TILEW);
            float acc[6][2][4];
#pragma unroll
            for (int mt = 0; mt < 6; mt++)
#pragma unroll
                for (int nt = 0; nt < 2; nt++)
#pragma unroll
                    for (int i = 0; i < 4; i++) acc[mt][nt][i] = 0.f;

#pragma unroll
            for (int kt = 0; kt < 4; kt++) {
                uint32_t bb0[2], bb1[2];
#pragma unroll
                for (int nt = 0; nt < 2; nt++) {
                    const int base = (nt * 8 + gq) * TILEW + kg * 32 + kt * 8 + tig;
                    bb0[nt] = ts[base];
                    bb1[nt] = ts[base + 4];
                }
#pragma unroll
                for (int mt = 0; mt < 6; mt++) {
                    mma_bf16(acc[mt][0], a[mt][kt][0], a[mt][kt][1], a[mt][kt][2], a[mt][kt][3], bb0[0], bb1[0]);
                    mma_bf16(acc[mt][1], a[mt][kt][0], a[mt][kt][1], a[mt][kt][2], a[mt][kt][3], bb0[1], bb1[1]);
                }
            }
#pragma unroll
            for (int mt = 0; mt < 6; mt++)
#pragma unroll
                for (int nt = 0; nt < 2; nt++) {
                    float* p = buf + (size_t)(kg * 96 + mt * 16 + gq) * BUFP2 + nt * 8 + 2 * tig;
                    *(float2*)p = make_float2(acc[mt][nt][0], acc[mt][nt][1]);
                    *(float2*)(p + 8 * BUFP2) = make_float2(acc[mt][nt][2], acc[mt][nt][3]);
                }
            __syncthreads();
        }

        // ---- gate combine: units (2jp, 2jp+1), batch b ----
        float rsA = 0.f, zsA = 0.f, nsA = 0.f;
        float rsB = 0.f, zsB = 0.f, nsB = 0.f;
        if (s > 0) {
#pragma unroll
            for (int q = 0; q < 8; q++) {
                const float* bq_ = buf + (size_t)(q * 96) * BUFP2;
                rsA += bq_[(2 * jp) * BUFP2 + b];       rsB += bq_[(2 * jp + 1) * BUFP2 + b];
                zsA += bq_[(32 + 2 * jp) * BUFP2 + b];  zsB += bq_[(33 + 2 * jp) * BUFP2 + b];
                nsA += bq_[(64 + 2 * jp) * BUFP2 + b];  nsB += bq_[(65 + 2 * jp) * BUFP2 + b];
            }
        }
        const float rgA = sigm_f(ir2.x + rsA + bbv[2 * jp]);
        const float zgA = sigm_f(iz2.x + zsA + bbv[32 + 2 * jp]);
        const float ngA = tanh_f(in2.x + rgA * (nsA + bbv[64 + 2 * jp]));
        const float hvA = (1.f - zgA) * ngA + zgA * hpA;
        const float rgB = sigm_f(ir2.y + rsB + bbv[2 * jp + 1]);
        const float zgB = sigm_f(iz2.y + zsB + bbv[33 + 2 * jp]);
        const float ngB = tanh_f(in2.y + rgB * (nsB + bbv[65 + 2 * jp]));
        const float hvB = (1.f - zgB) * ngB + zgB * hpB;
        hpA = hvA; hpB = hvB;

        *(float2*)(hout32 + ((size_t)s * B_ + b0 + b) * H_ + j0 + 2 * jp)
            = make_float2(hvA, hvB);

        // ---- publish: push bf16x2 into all 16 peers' tiles + arrive ----
        if (s < S_ - 1) {
            const uint32_t pk = pack_bf16(hvA, hvB);
            const uint32_t soff = (uint32_t)((s & 1) * (16 * TILEW * 4));
#pragma unroll
            for (int rk = 0; rk < 16; rk++)
                stsc_u32(ptb[rk] + soff + myoff, pk);
            __syncthreads();
            if (t < 16)
                mbar_arrive_peer((s & 1) ? mb1 : mb0, (unsigned)t);
        }
    }

    asm volatile("barrier.cluster.arrive.aligned;" ::: "memory");
    asm volatile("barrier.cluster.wait.aligned;" ::: "memory");
}

// =================================================================================
// Kernel B (fallback, R12): flag-based scan — used only if cluster launch fails.
// =================================================================================
#define BUFP 34
#define HOLDP 17
#define SMEM_FB_BYTES ((8 * 48 * BUFP + 32 * HOLDP + 64) * 4)

__global__ void __launch_bounds__(256, 1) gru_scan_fallback(
    const float* __restrict__ Whh_f, const float* __restrict__ bhh_f,
    const float* __restrict__ Whh_b, const float* __restrict__ bhh_b)
{
    extern __shared__ float sm[];
    float* buf  = sm;
    float* hold = buf + 8 * 48 * BUFP;
    __shared__ float bbv[48];
    __shared__ unsigned sbase;

    const int t    = threadIdx.x;
    const int lane = t & 31;
    const int kg   = t >> 5;
    const int gq   = lane >> 2;
    const int tig  = lane & 3;

    const int blk   = blockIdx.x;
    const int dir   = blk >> 6;
    const int r     = blk & 63;
    const int jblk  = r >> 1;
    const int bhalf = r & 1;
    const int j0    = jblk * 16;
    const int b0    = bhalf * 32;

    const float* Whh = dir ? Whh_b : Whh_f;
    const float* bhh = dir ? bhh_b : bhh_f;
    const float* gi  = dir ? g_gi_b : g_gi_f;
    float* hout32    = dir ? g_hb : g_hf;
    __nv_bfloat16* hout16 = dir ? g_h16b : g_h16f;

    if (t < 48) bbv[t] = bhh[(size_t)((t >> 4) * 512 + j0 + (t & 15))];
    if (t == 0) sbase = *(volatile unsigned*)&g_flag[dir][bhalf][jblk][0];

    uint32_t a[3][4][4];
#pragma unroll
    for (int g = 0; g < 3; g++) {
        const float* Wg = Whh + (size_t)(g * 512 + j0) * 512;
#pragma unroll
        for (int kt = 0; kt < 4; kt++) {
            const int kb = kg * 64 + kt * 16;
            const int c0 = kb + 2 * tig;
            const int c1 = kb + 8 + 2 * tig;
            a[g][kt][0] = pack_bf16(Wg[(size_t)gq * 512 + c0],      Wg[(size_t)gq * 512 + c0 + 1]);
            a[g][kt][1] = pack_bf16(Wg[(size_t)(gq + 8) * 512 + c0], Wg[(size_t)(gq + 8) * 512 + c0 + 1]);
            a[g][kt][2] = pack_bf16(Wg[(size_t)gq * 512 + c1],      Wg[(size_t)gq * 512 + c1 + 1]);
            a[g][kt][3] = pack_bf16(Wg[(size_t)(gq + 8) * 512 + c1], Wg[(size_t)(gq + 8) * 512 + c1 + 1]);
        }
    }
    __syncthreads();

    const unsigned sb = sbase;
    const int j1 = t & 15;
    const int m_ = t >> 4;
    const int bA = 2 * m_, bB = 2 * m_ + 1;

    for (int s = 0; s < S_; ++s) {
        const float* gis = gi + (size_t)s * (B_ * G3);
        const size_t gaA = (size_t)(b0 + bA) * G3 + j0 + j1;
        const size_t gaB = (size_t)(b0 + bB) * G3 + j0 + j1;
        const float irA = gis[gaA], izA = gis[gaA + 512], inA = gis[gaA + 1024];
        const float irB = gis[gaB], izB = gis[gaB + 512], inB = gis[gaB + 1024];

        if (s > 0) {
            const unsigned tgt = sb + (unsigned)s;
            if (lane < 4) {
                unsigned* fp = &g_flag[dir][bhalf][4 * kg + lane][0];
                while (ld_acquire(fp) < tgt) { }
            }
            __syncwarp();

            const uint32_t* hbase = (const uint32_t*)(hout16
                + (size_t)(s - 1) * (B_ * H_) + (size_t)b0 * H_);
            uint32_t bb[4][4][2];
#pragma unroll
            for (int nt = 0; nt < 4; nt++) {
                const uint32_t* hr = hbase + (size_t)(nt * 8 + gq) * (H_ / 2)
                                     + kg * 32 + tig;
#pragma unroll
                for (int kt = 0; kt < 4; kt++) {
                    bb[nt][kt][0] = hr[kt * 8];
                    bb[nt][kt][1] = hr[kt * 8 + 4];
                }
            }

            float acc[3][4][4];
#pragma unroll
            for (int g = 0; g < 3; g++)
#pragma unroll
                for (int nt = 0; nt < 4; nt++)
#pragma unroll
                    for (int i = 0; i < 4; i++) acc[g][nt][i] = 0.f;

#pragma unroll
            for (int kt = 0; kt < 4; kt++)
#pragma unroll
                for (int nt = 0; nt < 4; nt++)
#pragma unroll
                    for (int g = 0; g < 3; g++)
                        mma_bf16(acc[g][nt], a[g][kt][0], a[g][kt][1],
                                 a[g][kt][2], a[g][kt][3],
                                 bb[nt][kt][0], bb[nt][kt][1]);

#pragma unroll
            for (int g = 0; g < 3; g++) {
                float* bbp = buf + (size_t)(kg * 48 + g * 16) * BUFP;
#pragma unroll
                for (int nt = 0; nt < 4; nt++) {
                    const int c = nt * 8 + 2 * tig;
                    *(float2*)(bbp + gq * BUFP + c)       = make_float2(acc[g][nt][0], acc[g][nt][1]);
                    *(float2*)(bbp + (gq + 8) * BUFP + c) = make_float2(acc[g][nt][2], acc[g][nt][3]);
                }
            }
            __syncthreads();
        }

        float* hnew32 = hout32 + (size_t)s * (B_ * H_);
        __nv_bfloat16* hnew16 = hout16 + (size_t)s * (B_ * H_);

        float rsA = 0.f, zsA = 0.f, nsA = 0.f, hpA = 0.f;
        float rsB = 0.f, zsB = 0.f, nsB = 0.f, hpB = 0.f;
        if (s > 0) {
#pragma unroll
            for (int q = 0; q < 8; q++) {
                const float2 vr = *(const float2*)(buf + (q * 48 + j1) * BUFP + bA);
                const float2 vz = *(const float2*)(buf + (q * 48 + 16 + j1) * BUFP + bA);
                const float2 vn = *(const float2*)(buf + (q * 48 + 32 + j1) * BUFP + bA);
                rsA += vr.x; rsB += vr.y;
                zsA += vz.x; zsB += vz.y;
                nsA += vn.x; nsB += vn.y;
            }
            hpA = hold[bA * HOLDP + j1];
            hpB = hold[bB * HOLDP + j1];
        }
        {
            const float rg = sigm_f(irA + rsA + bbv[j1]);
            const float zg = sigm_f(izA + zsA + bbv[16 + j1]);
            const float ng = tanh_f(inA + rg * (nsA + bbv[32 + j1]));
            const float hv = (1.f - zg) * ng + zg * hpA;
            hnew32[(size_t)(b0 + bA) * H_ + j0 + j1] = hv;
            hnew16[(size_t)(b0 + bA) * H_ + j0 + j1] = __float2bfloat16(hv);
            hold[bA * HOLDP + j1] = hv;
        }
        {
            const float rg = sigm_f(irB + rsB + bbv[j1]);
            const float zg = sigm_f(izB + zsB + bbv[16 + j1]);
            const float ng = tanh_f(inB + rg * (nsB + bbv[32 + j1]));
            const float hv = (1.f - zg) * ng + zg * hpB;
            hnew32[(size_t)(b0 + bB) * H_ + j0 + j1] = hv;
            hnew16[(size_t)(b0 + bB) * H_ + j0 + j1] = __float2bfloat16(hv);
            hold[bB * HOLDP + j1] = hv;
        }

        if (s < S_ - 1) {
            __syncthreads();
            if (t == 0)
                st_release(&g_flag[dir][bhalf][jblk][0], sb + (unsigned)s + 1u);
        }
    }
}

// =================================================================================
// Kernel C: logits + log_softmax + transpose to [B,21,S]  [unchanged]
// =================================================================================
#define SMEM_C_BYTES ((NCLS * 1024 + 1024 + 32) * 4)

__global__ void __launch_bounds__(256, 1) head_kernel(
    const float* __restrict__ linW, const float* __restrict__ linb,
    float* __restrict__ out)
{
    extern __shared__ float sm[];
    float* Wsm = sm;
    float* row = Wsm + NCLS * 1024;
    float* lg  = row + 1024;

    const int t = threadIdx.x;
    for (int i = t; i < NCLS * 256; i += 256)
        ((float4*)Wsm)[i] = ((const float4*)linW)[i];
    __syncthreads();

    const int w = t >> 5, lane = t & 31;
    const int m0 = blockIdx.x * 8;

    for (int rr = 0; rr < 8; rr++) {
        const int m = m0 + rr;
        const int s = m >> 6, b = m & 63;
        const float* hf = g_hf + ((size_t)s * B_ + b) * H_;
        const float* hb = g_hb + ((size_t)(S_ - 1 - s) * B_ + b) * H_;
        ((float4*)row)[t] = (t < 128) ? ((const float4*)hf)[t]
                                      : ((const float4*)hb)[t - 128];
        __syncthreads();

#pragma unroll
        for (int j = 0; j < 3; j++) {
            const int c = w + 8 * j;
            if (c < NCLS) {
                float p = 0.f;
                const float* wc = Wsm + c * 1024;
#pragma unroll 4
                for (int k = lane; k < 1024; k += 32) p = fmaf(row[k], wc[k], p);
#pragma unroll
                for (int off = 16; off; off >>= 1) p += __shfl_xor_sync(0xffffffffu, p, off);
                if (lane == 0) lg[c] = p + linb[c];
            }
        }
        __syncthreads();
        if (t == 0) {
            float mx = lg[0];
            for (int c = 1; c < NCLS; c++) mx = fmaxf(mx, lg[c]);
            float sum = 0.f;
            for (int c = 0; c < NCLS; c++) sum += __expf(lg[c] - mx);
            lg[24] = mx + __logf(sum);
        }
        __syncthreads();
        if (t < NCLS)
            out[(size_t)b * (NCLS * S_) + (size_t)t * S_ + s] = lg[t] - lg[24];
        __syncthreads();
    }
}

// =================================================================================
extern "C" void kernel_launch(void* const* d_in, const int* in_sizes, int n_in,
                              void* d_out, int out_size)
{
    (void)in_sizes; (void)n_in; (void)out_size;
    const int*   idx     = (const int*)  d_in[0];
    const float* emb     = (const float*)d_in[1];
    const float* W_ih_f  = (const float*)d_in[2];
    const float* W_hh_f  = (const float*)d_in[3];
    const float* b_ih_f  = (const float*)d_in[4];
    const float* b_hh_f  = (const float*)d_in[5];
    const float* W_ih_b  = (const float*)d_in[6];
    const float* W_hh_b  = (const float*)d_in[7];
    const float* b_ih_b  = (const float*)d_in[8];
    const float* b_hh_b  = (const float*)d_in[9];
    const float* lin_W   = (const float*)d_in[10];
    const float* lin_b   = (const float*)d_in[11];
    float* out = (float*)d_out;

    cudaFuncSetAttribute(gi_gemm_kernel,   cudaFuncAttributeMaxDynamicSharedMemorySize, SMEM_A_BYTES);
    cudaFuncSetAttribute(gru_scan_cluster, cudaFuncAttributeMaxDynamicSharedMemorySize, SMEM_SC_BYTES);
    cudaFuncSetAttribute(gru_scan_cluster, cudaFuncAttributeNonPortableClusterSizeAllowed, 1);
    cudaFuncSetAttribute(gru_scan_fallback, cudaFuncAttributeMaxDynamicSharedMemorySize, SMEM_FB_BYTES);
    cudaFuncSetAttribute(head_kernel,      cudaFuncAttributeMaxDynamicSharedMemorySize, SMEM_C_BYTES);

    dim3 gA(24, 128);
    gi_gemm_kernel<<<gA, 256, SMEM_A_BYTES>>>(idx, emb, W_ih_f, b_ih_f, W_ih_b, b_ih_b);

    cudaLaunchConfig_t cfg = {};
    cfg.gridDim = dim3(128, 1, 1);
    cfg.blockDim = dim3(256, 1, 1);
    cfg.dynamicSmemBytes = SMEM_SC_BYTES;
    cfg.stream = 0;
    cudaLaunchAttribute attr[1];
    attr[0].id = cudaLaunchAttributeClusterDimension;
    attr[0].val.clusterDim.x = 16;
    attr[0].val.clusterDim.y = 1;
    attr[0].val.clusterDim.z = 1;
    cfg.attrs = attr;
    cfg.numAttrs = 1;
    cudaError_t e = cudaLaunchKernelEx(&cfg, gru_scan_cluster,
                                       W_hh_f, b_hh_f, W_hh_b, b_hh_b);
    if (e != cudaSuccess) {
        (void)cudaGetLastError();   // clear error state
        gru_scan_fallback<<<128, 256, SMEM_FB_BYTES>>>(W_hh_f, b_hh_f, W_hh_b, b_hh_b);
    }

    head_kernel<<<2048, 256, SMEM_C_BYTES>>>(lin_W, lin_b, out);
}

// round 16
// speedup vs baseline: 2.1513x; 2.1513x over previous
#include <cuda_runtime.h>
#include <cuda_bf16.h>
#include <math.h>
#include <stdint.h>

#define S_  256
#define B_  64
#define E_  300
#define H_  512
#define G3  1536          // 3*H
#define NCLS 21

// ---------------- scratch (device globals; no allocation allowed) ----------------
__device__ float g_gi_f[(size_t)S_ * B_ * G3];     // [s][b][1536]
__device__ float g_gi_b[(size_t)S_ * B_ * G3];     // backward, time-reversed storage
__device__ float g_hf[(size_t)S_ * B_ * H_];       // fp32 h for head
__device__ float g_hb[(size_t)S_ * B_ * H_];
__device__ __nv_bfloat16 g_h16f[(size_t)S_ * B_ * H_];  // bf16 h for scan exchange
__device__ __nv_bfloat16 g_h16b[(size_t)S_ * B_ * H_];
// per-producer monotonic flags: [dir][bq][jblk][pad]
__device__ unsigned g_flag2[2][4][16][8];

// ---------------- common helpers ----------------
__device__ __forceinline__ void mma_tf32(float c[4],
    uint32_t a0, uint32_t a1, uint32_t a2, uint32_t a3,
    uint32_t b0, uint32_t b1)
{
    asm volatile(
        "mma.sync.aligned.m16n8k8.row.col.f32.tf32.tf32.f32 "
        "{%0,%1,%2,%3},{%4,%5,%6,%7},{%8,%9},{%0,%1,%2,%3};"
        : "+f"(c[0]), "+f"(c[1]), "+f"(c[2]), "+f"(c[3])
        : "r"(a0), "r"(a1), "r"(a2), "r"(a3), "r"(b0), "r"(b1));
}

__device__ __forceinline__ void mma_bf16(float c[4],
    uint32_t a0, uint32_t a1, uint32_t a2, uint32_t a3,
    uint32_t b0, uint32_t b1)
{
    asm volatile(
        "mma.sync.aligned.m16n8k16.row.col.f32.bf16.bf16.f32 "
        "{%0,%1,%2,%3},{%4,%5,%6,%7},{%8,%9},{%0,%1,%2,%3};"
        : "+f"(c[0]), "+f"(c[1]), "+f"(c[2]), "+f"(c[3])
        : "r"(a0), "r"(a1), "r"(a2), "r"(a3), "r"(b0), "r"(b1));
}

__device__ __forceinline__ uint32_t pack_bf16(float lo, float hi) {
    uint32_t r;
    asm("cvt.rn.bf16x2.f32 %0, %1, %2;" : "=r"(r) : "f"(hi), "f"(lo));
    return r;
}

__device__ __forceinline__ unsigned ld_acquire(unsigned* p) {
    unsigned v;
    asm volatile("ld.acquire.gpu.global.u32 %0,[%1];" : "=r"(v) : "l"(p) : "memory");
    return v;
}

__device__ __forceinline__ void st_release(unsigned* p, unsigned v) {
    asm volatile("st.release.gpu.global.u32 [%0],%1;" :: "l"(p), "r"(v) : "memory");
}

__device__ __forceinline__ uint32_t smem_u32(const void* p) {
    uint32_t a;
    asm("{ .reg .u64 t; cvta.to.shared.u64 t, %1; cvt.u32.u64 %0, t; }"
        : "=r"(a) : "l"(p));
    return a;
}

__device__ __forceinline__ void cp_async16(uint32_t dst, const void* src, unsigned srcbytes) {
    asm volatile("cp.async.cg.shared.global [%0], [%1], 16, %2;"
                 :: "r"(dst), "l"(src), "r"(srcbytes));
}

__device__ __forceinline__ float sigm_f(float x) {
    return __fdividef(1.f, 1.f + __expf(-x));
}
__device__ __forceinline__ float tanh_f(float x) {
    const float ax = fabsf(x);
    const float e  = __expf(-2.f * ax);
    const float r  = __fdividef(1.f - e, 1.f + e);
    return copysignf(r, x);
}

// =================================================================================
// Kernel A: gi = gather(emb, idx) @ W_ih^T + b_ih — tf32 MMA, 3-stage cp.async
// ring, ONE __syncthreads per k-tile (reuse distance 3).  [R15: 336us]
// =================================================================================
#define TKP 20
#define SMEM_A_BYTES (2 * 3 * 128 * TKP * 4)

__global__ void __launch_bounds__(256, 2) gi_gemm_kernel(
    const int* __restrict__ idxmat, const float* __restrict__ emb,
    const float* __restrict__ Wf, const float* __restrict__ bf,
    const float* __restrict__ Wb, const float* __restrict__ bbias)
{
    extern __shared__ uint32_t gsm[];
    uint32_t (*As)[TKP] = (uint32_t (*)[TKP])(gsm);                    // [3*128][TKP]
    uint32_t (*Bs)[TKP] = (uint32_t (*)[TKP])(gsm + 3 * 128 * TKP);

    const int t    = threadIdx.x;
    const int n0   = blockIdx.x * 128;
    const int m0   = blockIdx.y * 128;
    const bool bwd = (n0 >= G3);

    const int lr = t & 127;       // row this thread copies
    const int kh = t >> 7;        // k-half (0 or 1)

    const int am = m0 + lr;
    const int srow = am >> 6, brow = am & 63;
    const float* arow = emb + (size_t)idxmat[brow * S_ + srow] * E_;

    const int ng = n0 + lr;
    const float* wrow = bwd ? (Wb + (size_t)(ng - G3) * E_)
                            : (Wf + (size_t)ng * E_);

    const int lane = t & 31;
    const int w    = t >> 5;
    const int gq   = lane >> 2, tig = lane & 3;
    const int mw   = (w & 3) * 32;
    const int nw   = (w >> 2) * 64;

    float acc[2][8][4];
#pragma unroll
    for (int mt = 0; mt < 2; mt++)
#pragma unroll
        for (int nt = 0; nt < 8; nt++)
#pragma unroll
            for (int i = 0; i < 4; i++) acc[mt][nt][i] = 0.f;

    const uint32_t sA0 = smem_u32(&As[lr][8 * kh]);
    const uint32_t sB0 = smem_u32(&Bs[lr][8 * kh]);
    const uint32_t bstr = 128 * TKP * 4;   // bytes per buffer

#define GI_ISSUE(TILE, BUF)                                            \
    {                                                                  \
        const int ka = (TILE) * 16 + 8 * kh;                           \
        const unsigned p0 = (ka < E_) ? 16u : 0u;                      \
        const unsigned p1 = (ka + 4 < E_) ? 16u : 0u;                  \
        cp_async16(sA0 + (BUF) * bstr,      arow + ka,     p0);        \
        cp_async16(sA0 + (BUF) * bstr + 16, arow + ka + 4, p1);        \
        cp_async16(sB0 + (BUF) * bstr,      wrow + ka,     p0);        \
        cp_async16(sB0 + (BUF) * bstr + 16, wrow + ka + 4, p1);        \
    }

    GI_ISSUE(0, 0); asm volatile("cp.async.commit_group;");
    GI_ISSUE(1, 1); asm volatile("cp.async.commit_group;");

    for (int tile = 0; tile < 19; tile++) {
        asm volatile("cp.async.wait_group 1;");
        __syncthreads();
        if (tile + 2 < 19) { GI_ISSUE(tile + 2, (tile + 2) % 3); }
        asm volatile("cp.async.commit_group;");

        const int bi = (tile % 3) * 128;
#pragma unroll
        for (int kt = 0; kt < 2; kt++) {
            const int kb = kt * 8;
            uint32_t a[2][4];
#pragma unroll
            for (int mt = 0; mt < 2; mt++) {
                const int mb = mw + mt * 16;
                a[mt][0] = As[bi + mb + gq][kb + tig];
                a[mt][1] = As[bi + mb + gq + 8][kb + tig];
                a[mt][2] = As[bi + mb + gq][kb + tig + 4];
                a[mt][3] = As[bi + mb + gq + 8][kb + tig + 4];
            }
#pragma unroll
            for (int nt = 0; nt < 8; nt++) {
                const int nb = nw + nt * 8 + gq;
                const uint32_t b0v = Bs[bi + nb][kb + tig];
                const uint32_t b1v = Bs[bi + nb][kb + tig + 4];
                mma_tf32(acc[0][nt], a[0][0], a[0][1], a[0][2], a[0][3], b0v, b1v);
                mma_tf32(acc[1][nt], a[1][0], a[1][1], a[1][2], a[1][3], b0v, b1v);
            }
        }
    }
#undef GI_ISSUE

    const float* bias = bwd ? bbias : bf;
    float* gbase = bwd ? g_gi_b : g_gi_f;
    const int nc0 = (bwd ? n0 - G3 : n0) + nw;

#pragma unroll
    for (int mt = 0; mt < 2; mt++) {
#pragma unroll
        for (int half = 0; half < 2; half++) {
            const int rm = m0 + mw + mt * 16 + gq + half * 8;
            const int si = rm >> 6, bi2 = rm & 63;
            const size_t mrow = bwd ? ((size_t)(S_ - 1 - si) * B_ + bi2) : (size_t)rm;
            float* dst = gbase + mrow * G3;
#pragma unroll
            for (int nt = 0; nt < 8; nt++) {
                const int c = nc0 + nt * 8 + 2 * tig;
                float2 v;
                v.x = acc[mt][nt][half * 2 + 0] + bias[c];
                v.y = acc[mt][nt][half * 2 + 1] + bias[c + 1];
                *(float2*)(dst + c) = v;
            }
        }
    }
}

// =================================================================================
// Kernel B: persistent bidirectional GRU scan — bf16 mma, L2 dataflow flags,
// coarse partition: 128 blocks = dir(2) x bq(4: 16 batches) x jblk(16: 32 units,
// 96 gate rows). Producer group = 16 blocks; each warp (k-eighth) polls only its
// 2 producers. B-fragments straight from gmem; h carry state in registers.
// =================================================================================
#define BUFP2 18
#define SMEM_B_BYTES ((8 * 96 * BUFP2 + 32) * 4)

__global__ void __launch_bounds__(256, 1) gru_scan_kernel(
    const float* __restrict__ Whh_f, const float* __restrict__ bhh_f,
    const float* __restrict__ Whh_b, const float* __restrict__ bhh_b)
{
    extern __shared__ float sm[];
    float* buf = sm;                         // [8*96][BUFP2] mma partials
    __shared__ float bbv[96];
    __shared__ unsigned sbase;

    const int t    = threadIdx.x;
    const int lane = t & 31;
    const int kg   = t >> 5;          // warp = k-eighth 0..7 (64 k values)
    const int gq   = lane >> 2;
    const int tig  = lane & 3;

    const int blk  = blockIdx.x;
    const int dir  = blk >> 6;
    const int r    = blk & 63;
    const int bq   = r >> 4;          // 0..3: batches 16*bq..16*bq+15
    const int jblk = r & 15;          // 0..15: units 32*jblk..32*jblk+31
    const int j0   = jblk * 32;
    const int b0   = bq * 16;

    const float* Whh = dir ? Whh_b : Whh_f;
    const float* bhh = dir ? bhh_b : bhh_f;
    const float* gi  = dir ? g_gi_b : g_gi_f;
    float* hout32    = dir ? g_hb : g_hf;
    __nv_bfloat16* hout16 = dir ? g_h16b : g_h16f;

    if (t < 96) bbv[t] = bhh[(size_t)((t >> 5) * 512 + j0 + (t & 31))];
    if (t == 0) sbase = *(volatile unsigned*)&g_flag2[dir][bq][jblk][0];

    // ---- register-resident bf16 A-fragments: a[mt][kt][4], 6 m16 tiles = 96 rows ----
    uint32_t a[6][4][4];
#pragma unroll
    for (int mt = 0; mt < 6; mt++) {
        const int rr1 = mt * 16 + gq;          // gate row 0..95
        const int rr2 = rr1 + 8;
        const float* w1 = Whh + (size_t)(((rr1 >> 5) << 9) + j0 + (rr1 & 31)) * 512;
        const float* w2 = Whh + (size_t)(((rr2 >> 5) << 9) + j0 + (rr2 & 31)) * 512;
#pragma unroll
        for (int kt = 0; kt < 4; kt++) {
            const int c0 = kg * 64 + kt * 16 + 2 * tig;
            const int c1 = c0 + 8;
            a[mt][kt][0] = pack_bf16(w1[c0], w1[c0 + 1]);
            a[mt][kt][1] = pack_bf16(w2[c0], w2[c0 + 1]);
            a[mt][kt][2] = pack_bf16(w1[c1], w1[c1 + 1]);
            a[mt][kt][3] = pack_bf16(w2[c1], w2[c1 + 1]);
        }
    }
    __syncthreads();

    const unsigned sb = sbase;

    // combine coordinates: thread -> (batch b, unit pair 2jp/2jp+1)
    const int b  = t & 15;            // 0..15
    const int jp = t >> 4;            // 0..15
    float hpA = 0.f, hpB = 0.f;       // fp32 carry state in registers

    for (int s = 0; s < S_; ++s) {
        // ---- prefetch gi[s] (overlaps flag wait) ----
        const float* gis = gi + (size_t)s * (B_ * G3);
        const size_t ga = (size_t)(b0 + b) * G3 + j0 + 2 * jp;
        const float2 ir2 = *(const float2*)(gis + ga);
        const float2 iz2 = *(const float2*)(gis + ga + 512);
        const float2 in2 = *(const float2*)(gis + ga + 1024);

        if (s > 0) {
            // ---- per-warp: wait for this warp's 2 producer blocks ----
            const unsigned tgt = sb + (unsigned)s;
            if (lane < 2) {
                unsigned* fp = &g_flag2[dir][bq][2 * kg + lane][0];
                while (ld_acquire(fp) < tgt) { }
            }
            __syncwarp();

            // ---- B-fragments straight from gmem (bf16x2 words) ----
            const uint32_t* hbase = (const uint32_t*)(hout16
                + (size_t)(s - 1) * (B_ * H_) + (size_t)b0 * H_);
            uint32_t bb0[2][4], bb1[2][4];    // [nt][kt]
#pragma unroll
            for (int nt = 0; nt < 2; nt++) {
                const uint32_t* hr = hbase + (size_t)(nt * 8 + gq) * (H_ / 2)
                                     + kg * 32 + tig;
#pragma unroll
                for (int kt = 0; kt < 4; kt++) {
                    bb0[nt][kt] = hr[kt * 8];
                    bb1[nt][kt] = hr[kt * 8 + 4];
                }
            }

            float acc[6][2][4];
#pragma unroll
            for (int mt = 0; mt < 6; mt++)
#pragma unroll
                for (int nt = 0; nt < 2; nt++)
#pragma unroll
                    for (int i = 0; i < 4; i++) acc[mt][nt][i] = 0.f;

#pragma unroll
            for (int kt = 0; kt < 4; kt++)
#pragma unroll
                for (int mt = 0; mt < 6; mt++) {
                    mma_bf16(acc[mt][0], a[mt][kt][0], a[mt][kt][1],
                             a[mt][kt][2], a[mt][kt][3], bb0[0][kt], bb1[0][kt]);
                    mma_bf16(acc[mt][1], a[mt][kt][0], a[mt][kt][1],
                             a[mt][kt][2], a[mt][kt][3], bb0[1][kt], bb1[1][kt]);
                }

#pragma unroll
            for (int mt = 0; mt < 6; mt++)
#pragma unroll
                for (int nt = 0; nt < 2; nt++) {
                    float* p = buf + (size_t)(kg * 96 + mt * 16 + gq) * BUFP2
                               + nt * 8 + 2 * tig;
                    *(float2*)p = make_float2(acc[mt][nt][0], acc[mt][nt][1]);
                    *(float2*)(p + 8 * BUFP2) = make_float2(acc[mt][nt][2], acc[mt][nt][3]);
                }
            __syncthreads();
        }

        // ---- gate combine: units (2jp, 2jp+1), batch b ----
        float rsA = 0.f, zsA = 0.f, nsA = 0.f;
        float rsB = 0.f, zsB = 0.f, nsB = 0.f;
        if (s > 0) {
#pragma unroll
            for (int q = 0; q < 8; q++) {
                const float* bq_ = buf + (size_t)(q * 96) * BUFP2;
                rsA += bq_[(2 * jp) * BUFP2 + b];       rsB += bq_[(2 * jp + 1) * BUFP2 + b];
                zsA += bq_[(32 + 2 * jp) * BUFP2 + b];  zsB += bq_[(33 + 2 * jp) * BUFP2 + b];
                nsA += bq_[(64 + 2 * jp) * BUFP2 + b];  nsB += bq_[(65 + 2 * jp) * BUFP2 + b];
            }
        }
        const float rgA = sigm_f(ir2.x + rsA + bbv[2 * jp]);
        const float zgA = sigm_f(iz2.x + zsA + bbv[32 + 2 * jp]);
        const float ngA = tanh_f(in2.x + rgA * (nsA + bbv[64 + 2 * jp]));
        const float hvA = (1.f - zgA) * ngA + zgA * hpA;
        const float rgB = sigm_f(ir2.y + rsB + bbv[2 * jp + 1]);
        const float zgB = sigm_f(iz2.y + zsB + bbv[33 + 2 * jp]);
        const float ngB = tanh_f(in2.y + rgB * (nsB + bbv[65 + 2 * jp]));
        const float hvB = (1.f - zgB) * ngB + zgB * hpB;
        hpA = hvA; hpB = hvB;

        // fp32 h for head; bf16x2 h for the scan exchange
        *(float2*)(hout32 + ((size_t)s * B_ + b0 + b) * H_ + j0 + 2 * jp)
            = make_float2(hvA, hvB);
        ((uint32_t*)(hout16 + ((size_t)s * B_ + b0 + b) * H_))[ (j0 >> 1) + jp ]
            = pack_bf16(hvA, hvB);

        // ---- publish: one release store per block ----
        if (s < S_ - 1) {
            __syncthreads();
            if (t == 0)
                st_release(&g_flag2[dir][bq][jblk][0], sb + (unsigned)s + 1u);
        }
    }
}

// =================================================================================
// Kernel C: logits + log_softmax + transpose to [B,21,S]  [unchanged]
// =================================================================================
#define SMEM_C_BYTES ((NCLS * 1024 + 1024 + 32) * 4)

__global__ void __launch_bounds__(256, 1) head_kernel(
    const float* __restrict__ linW, const float* __restrict__ linb,
    float* __restrict__ out)
{
    extern __shared__ float sm[];
    float* Wsm = sm;
    float* row = Wsm + NCLS * 1024;
    float* lg  = row + 1024;

    const int t = threadIdx.x;
    for (int i = t; i < NCLS * 256; i += 256)
        ((float4*)Wsm)[i] = ((const float4*)linW)[i];
    __syncthreads();

    const int w = t >> 5, lane = t & 31;
    const int m0 = blockIdx.x * 8;

    for (int rr = 0; rr < 8; rr++) {
        const int m = m0 + rr;
        const int s = m >> 6, b = m & 63;
        const float* hf = g_hf + ((size_t)s * B_ + b) * H_;
        const float* hb = g_hb + ((size_t)(S_ - 1 - s) * B_ + b) * H_;
        ((float4*)row)[t] = (t < 128) ? ((const float4*)hf)[t]
                                      : ((const float4*)hb)[t - 128];
        __syncthreads();

#pragma unroll
        for (int j = 0; j < 3; j++) {
            const int c = w + 8 * j;
            if (c < NCLS) {
                float p = 0.f;
                const float* wc = Wsm + c * 1024;
#pragma unroll 4
                for (int k = lane; k < 1024; k += 32) p = fmaf(row[k], wc[k], p);
#pragma unroll
                for (int off = 16; off; off >>= 1) p += __shfl_xor_sync(0xffffffffu, p, off);
                if (lane == 0) lg[c] = p + linb[c];
            }
        }
        __syncthreads();
        if (t == 0) {
            float mx = lg[0];
            for (int c = 1; c < NCLS; c++) mx = fmaxf(mx, lg[c]);
            float sum = 0.f;
            for (int c = 0; c < NCLS; c++) sum += __expf(lg[c] - mx);
            lg[24] = mx + __logf(sum);
        }
        __syncthreads();
        if (t < NCLS)
            out[(size_t)b * (NCLS * S_) + (size_t)t * S_ + s] = lg[t] - lg[24];
        __syncthreads();
    }
}

// =================================================================================
extern "C" void kernel_launch(void* const* d_in, const int* in_sizes, int n_in,
                              void* d_out, int out_size)
{
    (void)in_sizes; (void)n_in; (void)out_size;
    const int*   idx     = (const int*)  d_in[0];
    const float* emb     = (const float*)d_in[1];
    const float* W_ih_f  = (const float*)d_in[2];
    const float* W_hh_f  = (const float*)d_in[3];
    const float* b_ih_f  = (const float*)d_in[4];
    const float* b_hh_f  = (const float*)d_in[5];
    const float* W_ih_b  = (const float*)d_in[6];
    const float* W_hh_b  = (const float*)d_in[7];
    const float* b_ih_b  = (const float*)d_in[8];
    const float* b_hh_b  = (const float*)d_in[9];
    const float* lin_W   = (const float*)d_in[10];
    const float* lin_b   = (const float*)d_in[11];
    float* out = (float*)d_out;

    cudaFuncSetAttribute(gi_gemm_kernel,  cudaFuncAttributeMaxDynamicSharedMemorySize, SMEM_A_BYTES);
    cudaFuncSetAttribute(gru_scan_kernel, cudaFuncAttributeMaxDynamicSharedMemorySize, SMEM_B_BYTES);
    cudaFuncSetAttribute(head_kernel,     cudaFuncAttributeMaxDynamicSharedMemorySize, SMEM_C_BYTES);

    dim3 gA(24, 128);
    gi_gemm_kernel<<<gA, 256, SMEM_A_BYTES>>>(idx, emb, W_ih_f, b_ih_f, W_ih_b, b_ih_b);
    gru_scan_kernel<<<128, 256, SMEM_B_BYTES>>>(W_hh_f, b_hh_f, W_hh_b, b_hh_b);
    head_kernel<<<2048, 256, SMEM_C_BYTES>>>(lin_W, lin_b, out);
}

// round 17
// speedup vs baseline: 2.4019x; 1.1165x over previous
#include <cuda_runtime.h>
#include <cuda_bf16.h>
#include <math.h>
#include <stdint.h>

#define S_  256
#define B_  64
#define E_  300
#define H_  512
#define G3  1536          // 3*H
#define NCLS 21
#define KP16 320          // padded K for bf16 gi gemm (10 x BK32)

// ---------------- scratch (device globals; no allocation allowed) ----------------
__device__ float g_gi_f[(size_t)S_ * B_ * G3];     // [s][b][1536]
__device__ float g_gi_b[(size_t)S_ * B_ * G3];     // backward, time-reversed storage
__device__ float g_hf[(size_t)S_ * B_ * H_];       // fp32 h for head
__device__ float g_hb[(size_t)S_ * B_ * H_];
__device__ __nv_bfloat16 g_h16f[(size_t)S_ * B_ * H_];  // bf16 h for scan exchange
__device__ __nv_bfloat16 g_h16b[(size_t)S_ * B_ * H_];
__device__ __nv_bfloat16 g_x16[(size_t)(S_ * B_) * KP16];   // gathered emb, bf16, zero-pad
__device__ __nv_bfloat16 g_w16[(size_t)(2 * G3) * KP16];    // W_ih fwd|bwd, bf16, zero-pad
// per-producer monotonic flags: [dir][bq][jblk][pad]
__device__ unsigned g_flag2[2][4][16][8];

// ---------------- common helpers ----------------
__device__ __forceinline__ void mma_bf16(float c[4],
    uint32_t a0, uint32_t a1, uint32_t a2, uint32_t a3,
    uint32_t b0, uint32_t b1)
{
    asm volatile(
        "mma.sync.aligned.m16n8k16.row.col.f32.bf16.bf16.f32 "
        "{%0,%1,%2,%3},{%4,%5,%6,%7},{%8,%9},{%0,%1,%2,%3};"
        : "+f"(c[0]), "+f"(c[1]), "+f"(c[2]), "+f"(c[3])
        : "r"(a0), "r"(a1), "r"(a2), "r"(a3), "r"(b0), "r"(b1));
}

__device__ __forceinline__ uint32_t pack_bf16(float lo, float hi) {
    uint32_t r;
    asm("cvt.rn.bf16x2.f32 %0, %1, %2;" : "=r"(r) : "f"(hi), "f"(lo));
    return r;
}

__device__ __forceinline__ unsigned ld_acquire(unsigned* p) {
    unsigned v;
    asm volatile("ld.acquire.gpu.global.u32 %0,[%1];" : "=r"(v) : "l"(p) : "memory");
    return v;
}

__device__ __forceinline__ void st_release(unsigned* p, unsigned v) {
    asm volatile("st.release.gpu.global.u32 [%0],%1;" :: "l"(p), "r"(v) : "memory");
}

__device__ __forceinline__ uint32_t smem_u32(const void* p) {
    uint32_t a;
    asm("{ .reg .u64 t; cvta.to.shared.u64 t, %1; cvt.u32.u64 %0, t; }"
        : "=r"(a) : "l"(p));
    return a;
}

__device__ __forceinline__ void cp_async16(uint32_t dst, const void* src) {
    asm volatile("cp.async.cg.shared.global [%0], [%1], 16;"
                 :: "r"(dst), "l"(src));
}

__device__ __forceinline__ float sigm_f(float x) {
    return __fdividef(1.f, 1.f + __expf(-x));
}
__device__ __forceinline__ float tanh_f(float x) {
    const float ax = fabsf(x);
    const float e  = __expf(-2.f * ax);
    const float r  = __fdividef(1.f - e, 1.f + e);
    return copysignf(r, x);
}

// =================================================================================
// Kernel A0: gather + convert to bf16.
// rows [0, 16384): g_x16[m][k] = bf16(emb[idx[b][s]][k]), m = s*64+b, zero-pad k>=300
// rows [16384, 16384+3072): g_w16 = bf16(W_ih_f | W_ih_b), zero-pad
// 160 threads per row, each packs one bf16x2 word.
// =================================================================================
__global__ void __launch_bounds__(160, 8) convert_kernel(
    const int* __restrict__ idxmat, const float* __restrict__ emb,
    const float* __restrict__ Wf, const float* __restrict__ Wb)
{
    const int row = blockIdx.x;
    const int t   = threadIdx.x;       // 0..159 -> u32 index
    const int k   = 2 * t;

    const float* src;
    uint32_t* dst;
    if (row < S_ * B_) {
        const int srow = row >> 6, brow = row & 63;
        src = emb + (size_t)idxmat[brow * S_ + srow] * E_;
        dst = (uint32_t*)(g_x16 + (size_t)row * KP16);
    } else {
        const int wr = row - S_ * B_;
        src = (wr < G3) ? (Wf + (size_t)wr * E_) : (Wb + (size_t)(wr - G3) * E_);
        dst = (uint32_t*)(g_w16 + (size_t)wr * KP16);
    }
    const float v0 = (k     < E_) ? src[k]     : 0.f;
    const float v1 = (k + 1 < E_) ? src[k + 1] : 0.f;
    dst[t] = pack_bf16(v0, v1);
}

// =================================================================================
// Kernel A: gi = X16 @ W16^T + b_ih — bf16 m16n8k16 MMA, BK=32 (10 tiles),
// 3-stage cp.async ring, one __syncthreads per tile. Tile 128x128, 8 warps
// (warp tile 32x64). smem [row][k] pitch 20 u32 (16 payload + 4 pad).
// =================================================================================
#define TKP 20
#define SMEM_A_BYTES (2 * 3 * 128 * TKP * 4)

__global__ void __launch_bounds__(256, 2) gi_gemm_kernel(
    const float* __restrict__ bf, const float* __restrict__ bbias)
{
    extern __shared__ uint32_t gsm[];
    uint32_t (*As)[TKP] = (uint32_t (*)[TKP])(gsm);                    // [3*128][TKP]
    uint32_t (*Bs)[TKP] = (uint32_t (*)[TKP])(gsm + 3 * 128 * TKP);

    const int t    = threadIdx.x;
    const int n0   = blockIdx.x * 128;
    const int m0   = blockIdx.y * 128;
    const bool bwd = (n0 >= G3);

    const int lr = t & 127;       // row this thread copies
    const int kh = t >> 7;        // k-half: u32 offsets 8*kh + {0,4}

    const uint32_t* arow = (const uint32_t*)(g_x16 + (size_t)(m0 + lr) * KP16);
    const uint32_t* wrow = (const uint32_t*)(g_w16 + (size_t)(n0 + lr) * KP16);

    const int lane = t & 31;
    const int w    = t >> 5;
    const int gq   = lane >> 2, tig = lane & 3;
    const int mw   = (w & 3) * 32;
    const int nw   = (w >> 2) * 64;

    float acc[2][8][4];
#pragma unroll
    for (int mt = 0; mt < 2; mt++)
#pragma unroll
        for (int nt = 0; nt < 8; nt++)
#pragma unroll
            for (int i = 0; i < 4; i++) acc[mt][nt][i] = 0.f;

    const uint32_t sA0 = smem_u32(&As[lr][8 * kh]);
    const uint32_t sB0 = smem_u32(&Bs[lr][8 * kh]);
    const uint32_t bstr = 128 * TKP * 4;   // bytes per buffer

#define GI_ISSUE(TILE, BUF)                                            \
    {                                                                  \
        const int ku = (TILE) * 16 + 8 * kh;                           \
        cp_async16(sA0 + (BUF) * bstr,      arow + ku);                \
        cp_async16(sA0 + (BUF) * bstr + 16, arow + ku + 4);            \
        cp_async16(sB0 + (BUF) * bstr,      wrow + ku);                \
        cp_async16(sB0 + (BUF) * bstr + 16, wrow + ku + 4);            \
    }

    GI_ISSUE(0, 0); asm volatile("cp.async.commit_group;");
    GI_ISSUE(1, 1); asm volatile("cp.async.commit_group;");

    for (int tile = 0; tile < 10; tile++) {
        asm volatile("cp.async.wait_group 1;");
        __syncthreads();
        if (tile + 2 < 10) { GI_ISSUE(tile + 2, (tile + 2) % 3); }
        asm volatile("cp.async.commit_group;");

        const int bi = (tile % 3) * 128;
#pragma unroll
        for (int kt = 0; kt < 2; kt++) {
            const int kb = kt * 8;
            uint32_t a[2][4];
#pragma unroll
            for (int mt = 0; mt < 2; mt++) {
                const int mb = mw + mt * 16;
                a[mt][0] = As[bi + mb + gq][kb + tig];
                a[mt][1] = As[bi + mb + gq + 8][kb + tig];
                a[mt][2] = As[bi + mb + gq][kb + tig + 4];
                a[mt][3] = As[bi + mb + gq + 8][kb + tig + 4];
            }
#pragma unroll
            for (int nt = 0; nt < 8; nt++) {
                const int nb = nw + nt * 8 + gq;
                const uint32_t b0v = Bs[bi + nb][kb + tig];
                const uint32_t b1v = Bs[bi + nb][kb + tig + 4];
                mma_bf16(acc[0][nt], a[0][0], a[0][1], a[0][2], a[0][3], b0v, b1v);
                mma_bf16(acc[1][nt], a[1][0], a[1][1], a[1][2], a[1][3], b0v, b1v);
            }
        }
    }
#undef GI_ISSUE

    const float* bias = bwd ? bbias : bf;
    float* gbase = bwd ? g_gi_b : g_gi_f;
    const int nc0 = (bwd ? n0 - G3 : n0) + nw;

#pragma unroll
    for (int mt = 0; mt < 2; mt++) {
#pragma unroll
        for (int half = 0; half < 2; half++) {
            const int rm = m0 + mw + mt * 16 + gq + half * 8;
            const int si = rm >> 6, bi2 = rm & 63;
            const size_t mrow = bwd ? ((size_t)(S_ - 1 - si) * B_ + bi2) : (size_t)rm;
            float* dst = gbase + mrow * G3;
#pragma unroll
            for (int nt = 0; nt < 8; nt++) {
                const int c = nc0 + nt * 8 + 2 * tig;
                float2 v;
                v.x = acc[mt][nt][half * 2 + 0] + bias[c];
                v.y = acc[mt][nt][half * 2 + 1] + bias[c + 1];
                *(float2*)(dst + c) = v;
            }
        }
    }
}

// =================================================================================
// Kernel B: persistent bidirectional GRU scan — bf16 mma, L2 dataflow flags,
// 128 blocks = dir(2) x bq(4: 16 batches) x jblk(16: 32 units, 96 gate rows).
// Each warp (k-eighth) polls only its 2 producers. [R16: ~985us — unchanged]
// =================================================================================
#define BUFP2 18
#define SMEM_B_BYTES ((8 * 96 * BUFP2 + 32) * 4)

__global__ void __launch_bounds__(256, 1) gru_scan_kernel(
    const float* __restrict__ Whh_f, const float* __restrict__ bhh_f,
    const float* __restrict__ Whh_b, const float* __restrict__ bhh_b)
{
    extern __shared__ float sm[];
    float* buf = sm;                         // [8*96][BUFP2] mma partials
    __shared__ float bbv[96];
    __shared__ unsigned sbase;

    const int t    = threadIdx.x;
    const int lane = t & 31;
    const int kg   = t >> 5;          // warp = k-eighth 0..7 (64 k values)
    const int gq   = lane >> 2;
    const int tig  = lane & 3;

    const int blk  = blockIdx.x;
    const int dir  = blk >> 6;
    const int r    = blk & 63;
    const int bq   = r >> 4;          // 0..3: batches 16*bq..16*bq+15
    const int jblk = r & 15;          // 0..15: units 32*jblk..32*jblk+31
    const int j0   = jblk * 32;
    const int b0   = bq * 16;

    const float* Whh = dir ? Whh_b : Whh_f;
    const float* bhh = dir ? bhh_b : bhh_f;
    const float* gi  = dir ? g_gi_b : g_gi_f;
    float* hout32    = dir ? g_hb : g_hf;
    __nv_bfloat16* hout16 = dir ? g_h16b : g_h16f;

    if (t < 96) bbv[t] = bhh[(size_t)((t >> 5) * 512 + j0 + (t & 31))];
    if (t == 0) sbase = *(volatile unsigned*)&g_flag2[dir][bq][jblk][0];

    // ---- register-resident bf16 A-fragments: a[mt][kt][4], 6 m16 tiles = 96 rows ----
    uint32_t a[6][4][4];
#pragma unroll
    for (int mt = 0; mt < 6; mt++) {
        const int rr1 = mt * 16 + gq;          // gate row 0..95
        const int rr2 = rr1 + 8;
        const float* w1 = Whh + (size_t)(((rr1 >> 5) << 9) + j0 + (rr1 & 31)) * 512;
        const float* w2 = Whh + (size_t)(((rr2 >> 5) << 9) + j0 + (rr2 & 31)) * 512;
#pragma unroll
        for (int kt = 0; kt < 4; kt++) {
            const int c0 = kg * 64 + kt * 16 + 2 * tig;
            const int c1 = c0 + 8;
            a[mt][kt][0] = pack_bf16(w1[c0], w1[c0 + 1]);
            a[mt][kt][1] = pack_bf16(w2[c0], w2[c0 + 1]);
            a[mt][kt][2] = pack_bf16(w1[c1], w1[c1 + 1]);
            a[mt][kt][3] = pack_bf16(w2[c1], w2[c1 + 1]);
        }
    }
    __syncthreads();

    const unsigned sb = sbase;

    // combine coordinates: thread -> (batch b, unit pair 2jp/2jp+1)
    const int b  = t & 15;            // 0..15
    const int jp = t >> 4;            // 0..15
    float hpA = 0.f, hpB = 0.f;       // fp32 carry state in registers

    for (int s = 0; s < S_; ++s) {
        // ---- prefetch gi[s] (overlaps flag wait) ----
        const float* gis = gi + (size_t)s * (B_ * G3);
        const size_t ga = (size_t)(b0 + b) * G3 + j0 + 2 * jp;
        const float2 ir2 = *(const float2*)(gis + ga);
        const float2 iz2 = *(const float2*)(gis + ga + 512);
        const float2 in2 = *(const float2*)(gis + ga + 1024);

        if (s > 0) {
            // ---- per-warp: wait for this warp's 2 producer blocks ----
            const unsigned tgt = sb + (unsigned)s;
            if (lane < 2) {
                unsigned* fp = &g_flag2[dir][bq][2 * kg + lane][0];
                while (ld_acquire(fp) < tgt) { }
            }
            __syncwarp();

            // ---- B-fragments straight from gmem (bf16x2 words) ----
            const uint32_t* hbase = (const uint32_t*)(hout16
                + (size_t)(s - 1) * (B_ * H_) + (size_t)b0 * H_);
            uint32_t bb0[2][4], bb1[2][4];    // [nt][kt]
#pragma unroll
            for (int nt = 0; nt < 2; nt++) {
                const uint32_t* hr = hbase + (size_t)(nt * 8 + gq) * (H_ / 2)
                                     + kg * 32 + tig;
#pragma unroll
                for (int kt = 0; kt < 4; kt++) {
                    bb0[nt][kt] = hr[kt * 8];
                    bb1[nt][kt] = hr[kt * 8 + 4];
                }
            }

            float acc[6][2][4];
#pragma unroll
            for (int mt = 0; mt < 6; mt++)
#pragma unroll
                for (int nt = 0; nt < 2; nt++)
#pragma unroll
                    for (int i = 0; i < 4; i++) acc[mt][nt][i] = 0.f;

#pragma unroll
            for (int kt = 0; kt < 4; kt++)
#pragma unroll
                for (int mt = 0; mt < 6; mt++) {
                    mma_bf16(acc[mt][0], a[mt][kt][0], a[mt][kt][1],
                             a[mt][kt][2], a[mt][kt][3], bb0[0][kt], bb1[0][kt]);
                    mma_bf16(acc[mt][1], a[mt][kt][0], a[mt][kt][1],
                             a[mt][kt][2], a[mt][kt][3], bb0[1][kt], bb1[1][kt]);
                }

#pragma unroll
            for (int mt = 0; mt < 6; mt++)
#pragma unroll
                for (int nt = 0; nt < 2; nt++) {
                    float* p = buf + (size_t)(kg * 96 + mt * 16 + gq) * BUFP2
                               + nt * 8 + 2 * tig;
                    *(float2*)p = make_float2(acc[mt][nt][0], acc[mt][nt][1]);
                    *(float2*)(p + 8 * BUFP2) = make_float2(acc[mt][nt][2], acc[mt][nt][3]);
                }
            __syncthreads();
        }

        // ---- gate combine: units (2jp, 2jp+1), batch b ----
        float rsA = 0.f, zsA = 0.f, nsA = 0.f;
        float rsB = 0.f, zsB = 0.f, nsB = 0.f;
        if (s > 0) {
#pragma unroll
            for (int q = 0; q < 8; q++) {
                const float* bq_ = buf + (size_t)(q * 96) * BUFP2;
                rsA += bq_[(2 * jp) * BUFP2 + b];       rsB += bq_[(2 * jp + 1) * BUFP2 + b];
                zsA += bq_[(32 + 2 * jp) * BUFP2 + b];  zsB += bq_[(33 + 2 * jp) * BUFP2 + b];
                nsA += bq_[(64 + 2 * jp) * BUFP2 + b];  nsB += bq_[(65 + 2 * jp) * BUFP2 + b];
            }
        }
        const float rgA = sigm_f(ir2.x + rsA + bbv[2 * jp]);
        const float zgA = sigm_f(iz2.x + zsA + bbv[32 + 2 * jp]);
        const float ngA = tanh_f(in2.x + rgA * (nsA + bbv[64 + 2 * jp]));
        const float hvA = (1.f - zgA) * ngA + zgA * hpA;
        const float rgB = sigm_f(ir2.y + rsB + bbv[2 * jp + 1]);
        const float zgB = sigm_f(iz2.y + zsB + bbv[33 + 2 * jp]);
        const float ngB = tanh_f(in2.y + rgB * (nsB + bbv[65 + 2 * jp]));
        const float hvB = (1.f - zgB) * ngB + zgB * hpB;
        hpA = hvA; hpB = hvB;

        // fp32 h for head; bf16x2 h for the scan exchange
        *(float2*)(hout32 + ((size_t)s * B_ + b0 + b) * H_ + j0 + 2 * jp)
            = make_float2(hvA, hvB);
        ((uint32_t*)(hout16 + ((size_t)s * B_ + b0 + b) * H_))[ (j0 >> 1) + jp ]
            = pack_bf16(hvA, hvB);

        // ---- publish: one release store per block ----
        if (s < S_ - 1) {
            __syncthreads();
            if (t == 0)
                st_release(&g_flag2[dir][bq][jblk][0], sb + (unsigned)s + 1u);
        }
    }
}

// =================================================================================
// Kernel C: logits + log_softmax + transpose to [B,21,S]  [unchanged]
// =================================================================================
#define SMEM_C_BYTES ((NCLS * 1024 + 1024 + 32) * 4)

__global__ void __launch_bounds__(256, 1) head_kernel(
    const float* __restrict__ linW, const float* __restrict__ linb,
    float* __restrict__ out)
{
    extern __shared__ float sm[];
    float* Wsm = sm;
    float* row = Wsm + NCLS * 1024;
    float* lg  = row + 1024;

    const int t = threadIdx.x;
    for (int i = t; i < NCLS * 256; i += 256)
        ((float4*)Wsm)[i] = ((const float4*)linW)[i];
    __syncthreads();

    const int w = t >> 5, lane = t & 31;
    const int m0 = blockIdx.x * 8;

    for (int rr = 0; rr < 8; rr++) {
        const int m = m0 + rr;
        const int s = m >> 6, b = m & 63;
        const float* hf = g_hf + ((size_t)s * B_ + b) * H_;
        const float* hb = g_hb + ((size_t)(S_ - 1 - s) * B_ + b) * H_;
        ((float4*)row)[t] = (t < 128) ? ((const float4*)hf)[t]
                                      : ((const float4*)hb)[t - 128];
        __syncthreads();

#pragma unroll
        for (int j = 0; j < 3; j++) {
            const int c = w + 8 * j;
            if (c < NCLS) {
                float p = 0.f;
                const float* wc = Wsm + c * 1024;
#pragma unroll 4
                for (int k = lane; k < 1024; k += 32) p = fmaf(row[k], wc[k], p);
#pragma unroll
                for (int off = 16; off; off >>= 1) p += __shfl_xor_sync(0xffffffffu, p, off);
                if (lane == 0) lg[c] = p + linb[c];
            }
        }
        __syncthreads();
        if (t == 0) {
            float mx = lg[0];
            for (int c = 1; c < NCLS; c++) mx = fmaxf(mx, lg[c]);
            float sum = 0.f;
            for (int c = 0; c < NCLS; c++) sum += __expf(lg[c] - mx);
            lg[24] = mx + __logf(sum);
        }
        __syncthreads();
        if (t < NCLS)
            out[(size_t)b * (NCLS * S_) + (size_t)t * S_ + s] = lg[t] - lg[24];
        __syncthreads();
    }
}

// =================================================================================
extern "C" void kernel_launch(void* const* d_in, const int* in_sizes, int n_in,
                              void* d_out, int out_size)
{
    (void)in_sizes; (void)n_in; (void)out_size;
    const int*   idx     = (const int*)  d_in[0];
    const float* emb     = (const float*)d_in[1];
    const float* W_ih_f  = (const float*)d_in[2];
    const float* W_hh_f  = (const float*)d_in[3];
    const float* b_ih_f  = (const float*)d_in[4];
    const float* b_hh_f  = (const float*)d_in[5];
    const float* W_ih_b  = (const float*)d_in[6];
    const float* W_hh_b  = (const float*)d_in[7];
    const float* b_ih_b  = (const float*)d_in[8];
    const float* b_hh_b  = (const float*)d_in[9];
    const float* lin_W   = (const float*)d_in[10];
    const float* lin_b   = (const float*)d_in[11];
    float* out = (float*)d_out;

    cudaFuncSetAttribute(gi_gemm_kernel,  cudaFuncAttributeMaxDynamicSharedMemorySize, SMEM_A_BYTES);
    cudaFuncSetAttribute(gru_scan_kernel, cudaFuncAttributeMaxDynamicSharedMemorySize, SMEM_B_BYTES);
    cudaFuncSetAttribute(head_kernel,     cudaFuncAttributeMaxDynamicSharedMemorySize, SMEM_C_BYTES);

    convert_kernel<<<S_ * B_ + 2 * G3, 160>>>(idx, emb, W_ih_f, W_ih_b);
    dim3 gA(24, 128);
    gi_gemm_kernel<<<gA, 256, SMEM_A_BYTES>>>(b_ih_f, b_ih_b);
    gru_scan_kernel<<<128, 256, SMEM_B_BYTES>>>(W_hh_f, b_hh_f, W_hh_b, b_hh_b);
    head_kernel<<<2048, 256, SMEM_C_BYTES>>>(lin_W, lin_b, out);
}